// round 14
// baseline (speedup 1.0000x reference)
#include <cuda_runtime.h>

#define DD 512
#define NN 128
#define TPB 544
#define TINYF 1e-30f

// ---- packed f32x2 helpers (Blackwell FFMA2) ----
__device__ __forceinline__ unsigned long long fma2(unsigned long long a,
                                                   unsigned long long b,
                                                   unsigned long long c) {
    unsigned long long d;
    asm("fma.rn.f32x2 %0, %1, %2, %3;" : "=l"(d) : "l"(a), "l"(b), "l"(c));
    return d;
}
__device__ __forceinline__ float lo2(unsigned long long v) {
    return __uint_as_float((unsigned)v);
}
__device__ __forceinline__ float hi2(unsigned long long v) {
    return __uint_as_float((unsigned)(v >> 32));
}
__device__ __forceinline__ unsigned long long pack2(float x, float y) {
    unsigned long long d;
    asm("mov.b64 %0, {%1, %2};" : "=l"(d) : "f"(x), "f"(y));
    return d;
}

// Warp-specialized, one-step-deferred Woodbury sampler. ONE barrier/step.
//
// Warp 0 (sampler): decision_i (red_i = sum16(wred)+pivprev*c_{i-1}^2),
//   q_i = ysum + pivprev*c_{i-1}*q_{i-1}, c_i = q_i.up_{i+1} (1 warp-reduce),
//   P prefetch (4-step lead). Writes sh_piv/sh_c/sh_q/outputs.
// Warps 1-16 (B): bt = tid-32 owns row r=bt&127, cols [32h,32h+32), h=bt>>7.
//   fused: rb2 += (pivinv_{i-1}*q_{i-1}[r])*q_{i-1}[slice];
//          acc += rb2*up_{i+1}[slice]   (y_{i+1} partials)
//   tail: contrib = up_{i+1}[r]*ypart -> 5-shfl -> sh_wred[(i+1)&1].
// All shared cross-phase state double/triple buffered -> no intra-step races.
__global__ __launch_bounds__(TPB, 1)
void slater_sampler_kernel(const float* __restrict__ P,
                           const float* __restrict__ uin,
                           float* __restrict__ out,
                           int out_size)
{
    __shared__ __align__(16) float sh_up[3][NN];
    __shared__ __align__(16) float sh_part[2][512];
    __shared__ __align__(16) float sh_q[2][NN];
    __shared__ __align__(16) float sh_wred[2][16];
    __shared__ __align__(16) float sh_piv[2];
    __shared__ __align__(16) float sh_c[2];
    __shared__ __align__(16) float sh_u[NN];
    __shared__ int sh_kflag[2];

    const int tid  = threadIdx.x;
    const int lane = tid & 31;
    const int wid  = tid >> 5;
    const int bt   = tid - 32;           // B-thread index (wid >= 1)
    const int r    = bt & 127;
    const int h    = bt >> 7;
    const int cbase = 32 * h;
    const int pos_base = NN * DD;

    // ---- init output: cond_probs = 0, positions = -1 ----
    {
        int n4 = out_size >> 2;
        float4* o4 = (float4*)out;
        for (int idx = tid; idx < n4; idx += TPB) {
            int base = idx * 4;
            float4 v;
            v.x = (base + 0 < pos_base) ? 0.0f : -1.0f;
            v.y = (base + 1 < pos_base) ? 0.0f : -1.0f;
            v.z = (base + 2 < pos_base) ? 0.0f : -1.0f;
            v.w = (base + 3 < pos_base) ? 0.0f : -1.0f;
            o4[idx] = v;
        }
        for (int idx = (n4 << 2) + tid; idx < out_size; idx += TPB)
            out[idx] = (idx < pos_base) ? 0.0f : -1.0f;
    }

    if (tid < NN) {
        sh_u[tid]      = uin[tid];
        sh_up[1][tid]  = P[NN + tid];    // up_1
        sh_q[1][tid]   = 0.0f;           // q_{-1} = 0
    }
    if (tid == 0) {
        sh_piv[0] = 0.0f; sh_piv[1] = 0.0f;   // pivinv_{-1} = 0
        sh_c[0]   = 0.0f; sh_c[1]   = 0.0f;   // c_{-1} = 0
        sh_kflag[0] = 0;  sh_kflag[1] = 0;
    }

    // sampler-warp prefetch registers: pfA = up_2, pfB = up_3 (float4/lane)
    float4 pfA, pfB;
    if (wid == 0) {
        const float4* Pg = (const float4*)P;
        pfA = Pg[2 * 32 + lane];
        pfB = Pg[3 * 32 + lane];
    }

    // B slice = identity; prime sh_part[0] with y_0 = up_0, wred[0] with
    // partials of up_0 . y_0.
    unsigned long long rb2[16];
    if (wid >= 1) {
#pragma unroll
        for (int m = 0; m < 16; ++m) {
            unsigned long long v = 0ULL;
            int c0 = cbase + 2 * m;
            if (c0 == r)          v = 0x000000003f800000ULL;
            else if (c0 + 1 == r) v = 0x3f80000000000000ULL;
            rb2[m] = v;
        }
        float up0r = P[r];
        float mypart = (h == 0) ? up0r : 0.0f;
        sh_part[0][bt] = mypart;
        float contrib = up0r * mypart;
#pragma unroll
        for (int o = 16; o; o >>= 1)
            contrib += __shfl_xor_sync(0xffffffffu, contrib, o);
        if (lane == 0) sh_wred[0][wid - 1] = contrib;
    }
    __syncthreads();

    const bool write_pos = (pos_base + NN) <= out_size;

    // sampler-warp redundant state (identical across warp-0 lanes)
    float ratio = 1.0f, cumul = 0.0f, pivprev = 0.0f;
    int   k = 0;

    for (int i = 0; i < DD; ++i) {
        if (sh_kflag[(i + 1) & 1]) break;   // set by step i-1 (barrier passed)

        if (wid == 0) {
            // ================= SAMPLER WARP =================
            float cm1 = sh_c[(i + 1) & 1];          // c_{i-1}

            // decision_i: red = sum16(wred[i&1]) + pivprev*cm1^2
            float red;
            {
                const float4* w4 = (const float4*)sh_wred[i & 1];
                float4 w0 = w4[0], w1 = w4[1], w2 = w4[2], w3 = w4[3];
                red = (((w0.x + w0.y) + (w0.z + w0.w)) + ((w1.x + w1.y) + (w1.z + w1.w)))
                    + (((w2.x + w2.y) + (w2.z + w2.w)) + ((w3.x + w3.y) + (w3.z + w3.w)));
            }
            red += pivprev * cm1 * cm1;

            float s = 1.0f - red;
            int last_allowed = DD - NN + k;
            float p  = -(s - 1.0f) * ratio;
            float uk = sh_u[k < NN ? k : NN - 1];
            bool occupy = ((cumul + p) >= uk) || (i == last_allowed);
            float pivot = occupy ? (s - 1.0f) : s;
            if (fabsf(pivot) < TINYF) pivot = TINYF;
            float pivinv = 1.0f / pivot;

            if (lane == 0) {
                out[k * DD + i] = p;
                if (occupy && write_pos) out[pos_base + k] = (float)i;
                sh_piv[i & 1] = pivinv;
            }
            if (occupy) { ratio = 1.0f; cumul = 0.0f; ++k; }
            else        { ratio *= s;  cumul += p; }
            if (lane == 0 && k == NN) sh_kflag[i & 1] = 1;

            // q_i = ysum + (pivprev*cm1) * q_{i-1}   (rows 4*lane..4*lane+3)
            const float4* pp = (const float4*)sh_part[i & 1];
            float4 y0 = pp[lane];
            float4 y1 = pp[lane + 32];
            float4 y2 = pp[lane + 64];
            float4 y3 = pp[lane + 96];
            float4 qold = ((const float4*)sh_q[(i + 1) & 1])[lane];
            float cp = pivprev * cm1;
            float4 qi;
            qi.x = ((y0.x + y1.x) + (y2.x + y3.x)) + cp * qold.x;
            qi.y = ((y0.y + y1.y) + (y2.y + y3.y)) + cp * qold.y;
            qi.z = ((y0.z + y1.z) + (y2.z + y3.z)) + cp * qold.z;
            qi.w = ((y0.w + y1.w) + (y2.w + y3.w)) + cp * qold.w;
            ((float4*)sh_q[i & 1])[lane] = qi;

            // c_i = q_i . up_{i+1}
            float4 un = ((const float4*)sh_up[(i + 1) % 3])[lane];
            float cc = (qi.x * un.x + qi.y * un.y) + (qi.z * un.z + qi.w * un.w);
#pragma unroll
            for (int o = 16; o; o >>= 1)
                cc += __shfl_xor_sync(0xffffffffu, cc, o);
            if (lane == 0) sh_c[i & 1] = cc;

            // prefetch ring: STS up_{i+2}; slide pfA<-pfB; LDG up_{i+4}
            if (i + 2 < DD) ((float4*)sh_up[(i + 2) % 3])[lane] = pfA;
            pfA = pfB;
            if (i + 4 < DD) pfB = ((const float4*)P)[(i + 4) * 32 + lane];

            pivprev = pivinv;
        } else {
            // ================= B WARPS =================
            float pivm1 = sh_piv[(i + 1) & 1];      // pivinv_{i-1}
            const float* qprev = sh_q[(i + 1) & 1]; // q_{i-1}
            const float* upn   = sh_up[(i + 1) % 3];
            float upr = upn[r];
            float scale = pivm1 * qprev[r];
            unsigned long long s2 = pack2(scale, scale);
            const ulonglong2* q2 = (const ulonglong2*)(qprev + cbase);
            const ulonglong2* u2 = (const ulonglong2*)(upn + cbase);
            unsigned long long a0 = 0, a1 = 0, a2 = 0, a3 = 0;
#pragma unroll
            for (int j = 0; j < 4; ++j) {
                ulonglong2 qa = q2[2 * j];
                ulonglong2 qb = q2[2 * j + 1];
                ulonglong2 ua = u2[2 * j];
                ulonglong2 ub = u2[2 * j + 1];
                rb2[4 * j + 0] = fma2(s2, qa.x, rb2[4 * j + 0]);
                a0 = fma2(rb2[4 * j + 0], ua.x, a0);
                rb2[4 * j + 1] = fma2(s2, qa.y, rb2[4 * j + 1]);
                a1 = fma2(rb2[4 * j + 1], ua.y, a1);
                rb2[4 * j + 2] = fma2(s2, qb.x, rb2[4 * j + 2]);
                a2 = fma2(rb2[4 * j + 2], ub.x, a2);
                rb2[4 * j + 3] = fma2(s2, qb.y, rb2[4 * j + 3]);
                a3 = fma2(rb2[4 * j + 3], ub.y, a3);
            }
            float ypart = ((lo2(a0) + hi2(a0)) + (lo2(a1) + hi2(a1)))
                        + ((lo2(a2) + hi2(a2)) + (lo2(a3) + hi2(a3)));
            sh_part[(i + 1) & 1][bt] = ypart;

            float contrib = upr * ypart;
#pragma unroll
            for (int o = 16; o; o >>= 1)
                contrib += __shfl_xor_sync(0xffffffffu, contrib, o);
            if (lane == 0) sh_wred[(i + 1) & 1][wid - 1] = contrib;
        }

        __syncthreads();   // the ONLY barrier per step
    }
}

extern "C" void kernel_launch(void* const* d_in, const int* in_sizes, int n_in,
                              void* d_out, int out_size)
{
    const float* P = (const float*)d_in[0];   // (512, 128) row-major
    const float* u = (const float*)d_in[1];   // (128,)
    float* out = (float*)d_out;
    slater_sampler_kernel<<<1, TPB>>>(P, u, out, out_size);
}